// round 2
// baseline (speedup 1.0000x reference)
#include <cuda_runtime.h>
#include <cuda_bf16.h>
#include <cstdint>

// Problem constants (from reference)
#define NN 100000
#define FD 128
#define NE 1600000

// ---------------- Scratch (static __device__ — no allocation) ----------------
// NOTE: these are ONLY referenced from device code. Passing a __device__
// symbol as a host-side kernel argument passes the host shadow address (bug
// in round 1 -> illegal address -> zero output).
__device__ float g_h[(size_t)NN * FD];    // GEMM output / messages   (51.2 MB)
__device__ float g_agg[(size_t)NN * FD];  // aggregation buffer       (51.2 MB)
__device__ float g_ns[NN];                // deg_out -> norm_src
__device__ float g_nd[NN];                // deg_in  -> norm_dst

// ---------------- Small kernels ----------------

__global__ void zero_deg_kernel(int n) {
    int i = blockIdx.x * blockDim.x + threadIdx.x;
    if (i < n) { g_ns[i] = 0.f; g_nd[i] = 0.f; }
}

__global__ void degree_kernel(const int* __restrict__ src,
                              const int* __restrict__ dst, int E) {
    int i = blockIdx.x * blockDim.x + threadIdx.x;
    if (i < E) {
        atomicAdd(&g_ns[src[i]], 1.f);
        atomicAdd(&g_nd[dst[i]], 1.f);
    }
}

__global__ void norm_kernel(int n) {
    int i = blockIdx.x * blockDim.x + threadIdx.x;
    if (i < n) {
        g_ns[i] = rsqrtf(fmaxf(g_ns[i], 1.f));
        g_nd[i] = rsqrtf(fmaxf(g_nd[i], 1.f));
    }
}

__global__ void zero_agg_kernel(int n4) {
    int i = blockIdx.x * blockDim.x + threadIdx.x;
    if (i < n4) reinterpret_cast<float4*>(g_agg)[i] = make_float4(0.f, 0.f, 0.f, 0.f);
}

// ---------------- SGEMM: g_h = (A * g_ns[:,None]) @ W[128,128] ---------------
// A = Aext (layer 1: features) or g_agg (layer 2, Aext == nullptr).
// 128x128 tile, BK=32, 256 threads, 8x8 microtile per thread.
#define BM 128
#define BN 128
#define BK 32
#define APAD (BK + 1)

__global__ __launch_bounds__(256) void gemm_norm_kernel(
    const float* __restrict__ Aext, const float* __restrict__ W, int M) {
    const float* A = Aext ? Aext : g_agg;

    __shared__ float As[BM * APAD];  // [m][k], padded
    __shared__ float Bs[BK * BN];    // [k][n]

    const int tid = threadIdx.x;
    const int tx = tid & 15;   // 0..15 -> n block of 8
    const int ty = tid >> 4;   // 0..15 -> m block of 8
    const int row0 = blockIdx.x * BM;

    float acc[8][8];
#pragma unroll
    for (int i = 0; i < 8; i++)
#pragma unroll
        for (int j = 0; j < 8; j++) acc[i][j] = 0.f;

    for (int k0 = 0; k0 < FD; k0 += BK) {
        // Load A tile: 128 rows x 32 cols = 1024 float4, 4 per thread; fuse norm.
#pragma unroll
        for (int i = 0; i < 4; i++) {
            int id = tid + i * 256;
            int r = id >> 3;        // row within tile (8 float4 per row)
            int c4 = id & 7;        // which float4 along k
            int grow = row0 + r;
            float4 v = make_float4(0.f, 0.f, 0.f, 0.f);
            float nm = 0.f;
            if (grow < M) {
                v = *reinterpret_cast<const float4*>(A + (size_t)grow * FD + k0 + c4 * 4);
                nm = g_ns[grow];
            }
            float* dstp = &As[r * APAD + c4 * 4];
            dstp[0] = v.x * nm; dstp[1] = v.y * nm;
            dstp[2] = v.z * nm; dstp[3] = v.w * nm;
        }
        // Load B tile: 32 rows x 128 cols = 1024 float4, 4 per thread.
#pragma unroll
        for (int i = 0; i < 4; i++) {
            int id = tid + i * 256;
            int r = id >> 5;        // 32 float4 per row
            int c4 = id & 31;
            float4 v = *reinterpret_cast<const float4*>(W + (size_t)(k0 + r) * FD + c4 * 4);
            *reinterpret_cast<float4*>(&Bs[r * BN + c4 * 4]) = v;
        }
        __syncthreads();

#pragma unroll
        for (int kk = 0; kk < BK; kk++) {
            float a[8], b[8];
#pragma unroll
            for (int i = 0; i < 8; i++) a[i] = As[(ty * 8 + i) * APAD + kk];
            float4 b0 = *reinterpret_cast<const float4*>(&Bs[kk * BN + tx * 8]);
            float4 b1 = *reinterpret_cast<const float4*>(&Bs[kk * BN + tx * 8 + 4]);
            b[0] = b0.x; b[1] = b0.y; b[2] = b0.z; b[3] = b0.w;
            b[4] = b1.x; b[5] = b1.y; b[6] = b1.z; b[7] = b1.w;
#pragma unroll
            for (int i = 0; i < 8; i++)
#pragma unroll
                for (int j = 0; j < 8; j++) acc[i][j] += a[i] * b[j];
        }
        __syncthreads();
    }

#pragma unroll
    for (int i = 0; i < 8; i++) {
        int grow = row0 + ty * 8 + i;
        if (grow < M) {
            float4* cp = reinterpret_cast<float4*>(g_h + (size_t)grow * FD + tx * 8);
            cp[0] = make_float4(acc[i][0], acc[i][1], acc[i][2], acc[i][3]);
            cp[1] = make_float4(acc[i][4], acc[i][5], acc[i][6], acc[i][7]);
        }
    }
}

// ---------------- Edge scatter: g_agg[dst] += g_h[src], red.v4 ---------------
// One warp per edge (32 lanes x float4 = 128 floats). 8 edges per 256-thr block.
__global__ __launch_bounds__(256) void scatter_kernel(
    const int* __restrict__ src, const int* __restrict__ dst, int E) {
    const int lane = threadIdx.x & 31;
    const int warp = threadIdx.x >> 5;
    const int e = blockIdx.x * 8 + warp;
    if (e >= E) return;
    const int s = __ldg(&src[e]);
    const int d = __ldg(&dst[e]);
    const float4* hp = reinterpret_cast<const float4*>(g_h + (size_t)s * FD);
    float4 v = __ldg(&hp[lane]);
    float* ap = g_agg + (size_t)d * FD + lane * 4;
    asm volatile("red.global.add.v4.f32 [%0], {%1,%2,%3,%4};"
                 :: "l"(ap), "f"(v.x), "f"(v.y), "f"(v.z), "f"(v.w)
                 : "memory");
}

// ---------------- Epilogues ----------------
// layer 1: g_agg = relu(g_agg * g_nd + b)   (in place; becomes layer-2 input)
__global__ void post_relu_kernel(const float* __restrict__ b, int n) {
    int i = blockIdx.x * blockDim.x + threadIdx.x;
    if (i < n) {
        int node = i >> 7;
        int f = i & 127;
        float v = g_agg[i] * g_nd[node] + b[f];
        g_agg[i] = fmaxf(v, 0.f);
    }
}

// layer 2 final: out = g_agg * g_nd + b
__global__ void post_final_kernel(const float* __restrict__ b,
                                  float* __restrict__ out, int n) {
    int i = blockIdx.x * blockDim.x + threadIdx.x;
    if (i < n) {
        int node = i >> 7;
        int f = i & 127;
        out[i] = g_agg[i] * g_nd[node] + b[f];
    }
}

// ---------------- Launch ----------------
extern "C" void kernel_launch(void* const* d_in, const int* in_sizes, int n_in,
                              void* d_out, int out_size) {
    const float* features = (const float*)d_in[0];
    const int* src = (const int*)d_in[1];
    const int* dst = (const int*)d_in[2];
    const float* W1 = (const float*)d_in[3];
    const float* b1 = (const float*)d_in[4];
    const float* W2 = (const float*)d_in[5];
    const float* b2 = (const float*)d_in[6];
    float* out = (float*)d_out;

    const int M = in_sizes[0] / FD;   // 100000
    const int E = in_sizes[1];        // 1600000
    const int NF = M * FD;            // 12.8M
    const int NF4 = NF / 4;

    const int T = 256;
    // degrees + norms
    zero_deg_kernel<<<(M + T - 1) / T, T>>>(M);
    degree_kernel<<<(E + T - 1) / T, T>>>(src, dst, E);
    norm_kernel<<<(M + T - 1) / T, T>>>(M);

    const int gemm_blocks = (M + BM - 1) / BM;

    // Layer 1: h = (x * ns) @ W1 ; agg = scatter(h) ; agg = relu(agg*nd + b1)
    gemm_norm_kernel<<<gemm_blocks, 256>>>(features, W1, M);
    zero_agg_kernel<<<(NF4 + T - 1) / T, T>>>(NF4);
    scatter_kernel<<<(E + 7) / 8, 256>>>(src, dst, E);
    post_relu_kernel<<<(NF + T - 1) / T, T>>>(b1, NF);

    // Layer 2: h = (agg * ns) @ W2 ; agg2 = scatter(h) ; out = agg2*nd + b2
    gemm_norm_kernel<<<gemm_blocks, 256>>>(nullptr, W2, M);
    zero_agg_kernel<<<(NF4 + T - 1) / T, T>>>(NF4);
    scatter_kernel<<<(E + 7) / 8, 256>>>(src, dst, E);
    post_final_kernel<<<(NF + T - 1) / T, T>>>(b2, out, NF);
}

// round 3
// speedup vs baseline: 2.0743x; 2.0743x over previous
#include <cuda_runtime.h>
#include <cuda_bf16.h>
#include <cstdint>

// Problem constants
#define NN 100000
#define FD 128
#define NEMAX 1600000
#define SCAN_BS 256
#define NB1 ((NN + SCAN_BS - 1) / SCAN_BS)   // 391

// ---------------- Scratch (static __device__, device-code access only) ------
__device__ float g_h[(size_t)NN * FD];    // GEMM output / messages   (51.2 MB)
__device__ float g_agg[(size_t)NN * FD];  // layer-1 activation       (51.2 MB)
__device__ float g_ns[NN];                // norm_src
__device__ float g_nd[NN];                // norm_dst
__device__ int   g_co[NN];                // out-degree (src histogram)
__device__ int   g_ci[NN];                // in-degree  (dst histogram)
__device__ int   g_rowptr[NN + 1];        // CSR row pointers (by dst)
__device__ int   g_cursor[NN];            // fill cursors
__device__ int   g_esrc[NEMAX];           // CSR: src index per bucketed edge
__device__ int   g_bsum[NB1];             // scan block sums

// ---------------- Degree / norms ----------------
__global__ void zero_cnt_kernel(int n) {
    int i = blockIdx.x * blockDim.x + threadIdx.x;
    if (i < n) { g_co[i] = 0; g_ci[i] = 0; }
}

__global__ void degree_kernel(const int* __restrict__ src,
                              const int* __restrict__ dst, int E) {
    int i = blockIdx.x * blockDim.x + threadIdx.x;
    if (i < E) {
        atomicAdd(&g_co[src[i]], 1);
        atomicAdd(&g_ci[dst[i]], 1);
    }
}

__global__ void norm_kernel(int n) {
    int i = blockIdx.x * blockDim.x + threadIdx.x;
    if (i < n) {
        g_ns[i] = rsqrtf(fmaxf((float)g_co[i], 1.f));
        g_nd[i] = rsqrtf(fmaxf((float)g_ci[i], 1.f));
    }
}

// ---------------- Exclusive scan of g_ci -> g_rowptr ----------------
__global__ void scan1_kernel(int n) {
    __shared__ int s[SCAN_BS];
    int t = threadIdx.x, i = blockIdx.x * SCAN_BS + t;
    int v = (i < n) ? g_ci[i] : 0;
    s[t] = v; __syncthreads();
#pragma unroll
    for (int off = 1; off < SCAN_BS; off <<= 1) {
        int x = (t >= off) ? s[t - off] : 0; __syncthreads();
        s[t] += x; __syncthreads();
    }
    if (i < n) g_rowptr[i] = s[t] - v;               // exclusive within block
    if (t == SCAN_BS - 1) g_bsum[blockIdx.x] = s[t]; // block total
}

__global__ void scan2_kernel(int nb) {
    __shared__ int s[512];
    int t = threadIdx.x;
    int v = (t < nb) ? g_bsum[t] : 0;
    s[t] = v; __syncthreads();
#pragma unroll
    for (int off = 1; off < 512; off <<= 1) {
        int x = (t >= off) ? s[t - off] : 0; __syncthreads();
        s[t] += x; __syncthreads();
    }
    if (t < nb) g_bsum[t] = s[t] - v;                // exclusive
}

__global__ void scan3_kernel(int n, int E) {
    int i = blockIdx.x * blockDim.x + threadIdx.x;
    if (i < n) {
        int r = g_rowptr[i] + g_bsum[i >> 8];
        g_rowptr[i] = r;
        g_cursor[i] = r;
    }
    if (i == 0) g_rowptr[n] = E;
}

// ---------------- CSR fill: bucket edges by dst ----------------
__global__ void fill_kernel(const int* __restrict__ src,
                            const int* __restrict__ dst, int E) {
    int e = blockIdx.x * blockDim.x + threadIdx.x;
    if (e < E) {
        int d = dst[e];
        int pos = atomicAdd(&g_cursor[d], 1);
        g_esrc[pos] = src[e];
    }
}

// ---------------- SGEMM: g_h = (A * g_ns[:,None]) @ W[128,128] ---------------
#define BM 128
#define BN 128
#define BK 32
#define APAD (BK + 1)

__global__ __launch_bounds__(256, 2) void gemm_norm_kernel(
    const float* __restrict__ Aext, const float* __restrict__ W, int M) {
    const float* A = Aext ? Aext : g_agg;

    __shared__ float As[BM * APAD];
    __shared__ float Bs[BK * BN];

    const int tid = threadIdx.x;
    const int tx = tid & 15;
    const int ty = tid >> 4;
    const int row0 = blockIdx.x * BM;

    float acc[8][8];
#pragma unroll
    for (int i = 0; i < 8; i++)
#pragma unroll
        for (int j = 0; j < 8; j++) acc[i][j] = 0.f;

    for (int k0 = 0; k0 < FD; k0 += BK) {
#pragma unroll
        for (int i = 0; i < 4; i++) {
            int id = tid + i * 256;
            int r = id >> 3;
            int c4 = id & 7;
            int grow = row0 + r;
            float4 v = make_float4(0.f, 0.f, 0.f, 0.f);
            float nm = 0.f;
            if (grow < M) {
                v = *reinterpret_cast<const float4*>(A + (size_t)grow * FD + k0 + c4 * 4);
                nm = g_ns[grow];
            }
            float* dstp = &As[r * APAD + c4 * 4];
            dstp[0] = v.x * nm; dstp[1] = v.y * nm;
            dstp[2] = v.z * nm; dstp[3] = v.w * nm;
        }
#pragma unroll
        for (int i = 0; i < 4; i++) {
            int id = tid + i * 256;
            int r = id >> 5;
            int c4 = id & 31;
            float4 v = *reinterpret_cast<const float4*>(W + (size_t)(k0 + r) * FD + c4 * 4);
            *reinterpret_cast<float4*>(&Bs[r * BN + c4 * 4]) = v;
        }
        __syncthreads();

#pragma unroll
        for (int kk = 0; kk < BK; kk++) {
            float a[8], b[8];
#pragma unroll
            for (int i = 0; i < 8; i++) a[i] = As[(ty * 8 + i) * APAD + kk];
            float4 b0 = *reinterpret_cast<const float4*>(&Bs[kk * BN + tx * 8]);
            float4 b1 = *reinterpret_cast<const float4*>(&Bs[kk * BN + tx * 8 + 4]);
            b[0] = b0.x; b[1] = b0.y; b[2] = b0.z; b[3] = b0.w;
            b[4] = b1.x; b[5] = b1.y; b[6] = b1.z; b[7] = b1.w;
#pragma unroll
            for (int i = 0; i < 8; i++)
#pragma unroll
                for (int j = 0; j < 8; j++) acc[i][j] += a[i] * b[j];
        }
        __syncthreads();
    }

#pragma unroll
    for (int i = 0; i < 8; i++) {
        int grow = row0 + ty * 8 + i;
        if (grow < M) {
            float4* cp = reinterpret_cast<float4*>(g_h + (size_t)grow * FD + tx * 8);
            cp[0] = make_float4(acc[i][0], acc[i][1], acc[i][2], acc[i][3]);
            cp[1] = make_float4(acc[i][4], acc[i][5], acc[i][6], acc[i][7]);
        }
    }
}

// ---------------- CSR aggregate + fused epilogue ----------------
// One warp per node. acc = sum_{e in bucket(node)} g_h[src_e]   (float4/lane)
// then acc = acc * nd[node] + b ; optional ReLU ; write g_agg or out.
__global__ __launch_bounds__(256) void agg_kernel(
    const float* __restrict__ bvec, float* __restrict__ out,
    int M, int do_relu) {
    const int warp = (blockIdx.x * blockDim.x + threadIdx.x) >> 5;
    const int lane = threadIdx.x & 31;
    if (warp >= M) return;

    const int beg = g_rowptr[warp];
    const int end = g_rowptr[warp + 1];

    float4 acc = make_float4(0.f, 0.f, 0.f, 0.f);
    int j = beg;
    // 2-way unrolled for MLP
    for (; j + 1 < end; j += 2) {
        int s0 = __ldg(&g_esrc[j]);
        int s1 = __ldg(&g_esrc[j + 1]);
        float4 v0 = __ldg(reinterpret_cast<const float4*>(g_h + (size_t)s0 * FD) + lane);
        float4 v1 = __ldg(reinterpret_cast<const float4*>(g_h + (size_t)s1 * FD) + lane);
        acc.x += v0.x + v1.x; acc.y += v0.y + v1.y;
        acc.z += v0.z + v1.z; acc.w += v0.w + v1.w;
    }
    if (j < end) {
        int s0 = __ldg(&g_esrc[j]);
        float4 v0 = __ldg(reinterpret_cast<const float4*>(g_h + (size_t)s0 * FD) + lane);
        acc.x += v0.x; acc.y += v0.y; acc.z += v0.z; acc.w += v0.w;
    }

    const float nd = g_nd[warp];
    const float4 bb = __ldg(reinterpret_cast<const float4*>(bvec) + lane);
    acc.x = acc.x * nd + bb.x; acc.y = acc.y * nd + bb.y;
    acc.z = acc.z * nd + bb.z; acc.w = acc.w * nd + bb.w;
    if (do_relu) {
        acc.x = fmaxf(acc.x, 0.f); acc.y = fmaxf(acc.y, 0.f);
        acc.z = fmaxf(acc.z, 0.f); acc.w = fmaxf(acc.w, 0.f);
    }
    float* dstrow = out ? out : g_agg;
    reinterpret_cast<float4*>(dstrow + (size_t)warp * FD)[lane] = acc;
}

// ---------------- Launch ----------------
extern "C" void kernel_launch(void* const* d_in, const int* in_sizes, int n_in,
                              void* d_out, int out_size) {
    const float* features = (const float*)d_in[0];
    const int* src = (const int*)d_in[1];
    const int* dst = (const int*)d_in[2];
    const float* W1 = (const float*)d_in[3];
    const float* b1 = (const float*)d_in[4];
    const float* W2 = (const float*)d_in[5];
    const float* b2 = (const float*)d_in[6];
    float* out = (float*)d_out;

    const int M = in_sizes[0] / FD;   // 100000
    const int E = in_sizes[1];        // 1600000

    const int T = 256;
    const int mb = (M + T - 1) / T;
    const int eb = (E + T - 1) / T;

    // Degrees, norms, CSR build
    zero_cnt_kernel<<<mb, T>>>(M);
    degree_kernel<<<eb, T>>>(src, dst, E);
    norm_kernel<<<mb, T>>>(M);
    scan1_kernel<<<NB1, SCAN_BS>>>(M);
    scan2_kernel<<<1, 512>>>(NB1);
    scan3_kernel<<<mb, T>>>(M, E);
    fill_kernel<<<eb, T>>>(src, dst, E);

    const int gemm_blocks = (M + BM - 1) / BM;
    const int agg_blocks = (M * 32 + T - 1) / T;   // one warp per node

    // Layer 1
    gemm_norm_kernel<<<gemm_blocks, 256>>>(features, W1, M);
    agg_kernel<<<agg_blocks, T>>>(b1, nullptr, M, 1);

    // Layer 2
    gemm_norm_kernel<<<gemm_blocks, 256>>>(nullptr, W2, M);
    agg_kernel<<<agg_blocks, T>>>(b2, out, M, 0);
}

// round 5
// speedup vs baseline: 2.0882x; 1.0067x over previous
#include <cuda_runtime.h>
#include <cuda_bf16.h>
#include <cstdint>

// Problem constants
#define NN 100000
#define FD 128
#define NEMAX 1600000
#define SCAN_BS 256
#define NB1 ((NN + SCAN_BS - 1) / SCAN_BS)   // 391

// ---------------- Scratch (static __device__, device-code access only) ------
__device__ float g_h[(size_t)NN * FD];    // GEMM output / messages
__device__ float g_agg[(size_t)NN * FD];  // layer-1 activation
__device__ float g_ns[NN];                // norm_src
__device__ float g_nd[NN];                // norm_dst
__device__ int   g_co[NN];
__device__ int   g_ci[NN];
__device__ int   g_rowptr[NN + 1];
__device__ int   g_cursor[NN];
__device__ int   g_esrc[NEMAX];
__device__ int   g_bsum[NB1];

// ---------------- f32x2 packed-FMA helpers (base PTX, sm_100+ family) -------
__device__ __forceinline__ void ffma2(float2& d, const float2& a, const float2& b) {
    unsigned long long* dp = reinterpret_cast<unsigned long long*>(&d);
    asm("fma.rn.f32x2 %0, %1, %2, %0;"
        : "+l"(*dp)
        : "l"(*reinterpret_cast<const unsigned long long*>(&a)),
          "l"(*reinterpret_cast<const unsigned long long*>(&b)));
}
__device__ __forceinline__ float2 dup2(float a) {
    float2 r;
    asm("mov.b64 %0, {%1, %1};"
        : "=l"(*reinterpret_cast<unsigned long long*>(&r)) : "f"(a));
    return r;
}

// ---------------- Degree / norms / CSR build ----------------
__global__ void zero_cnt_kernel(int n) {
    int i = blockIdx.x * blockDim.x + threadIdx.x;
    if (i < n) { g_co[i] = 0; g_ci[i] = 0; }
}
__global__ void degree_kernel(const int* __restrict__ src,
                              const int* __restrict__ dst, int E) {
    int i = blockIdx.x * blockDim.x + threadIdx.x;
    if (i < E) { atomicAdd(&g_co[src[i]], 1); atomicAdd(&g_ci[dst[i]], 1); }
}
__global__ void norm_kernel(int n) {
    int i = blockIdx.x * blockDim.x + threadIdx.x;
    if (i < n) {
        g_ns[i] = rsqrtf(fmaxf((float)g_co[i], 1.f));
        g_nd[i] = rsqrtf(fmaxf((float)g_ci[i], 1.f));
    }
}
__global__ void scan1_kernel(int n) {
    __shared__ int s[SCAN_BS];
    int t = threadIdx.x, i = blockIdx.x * SCAN_BS + t;
    int v = (i < n) ? g_ci[i] : 0;
    s[t] = v; __syncthreads();
#pragma unroll
    for (int off = 1; off < SCAN_BS; off <<= 1) {
        int x = (t >= off) ? s[t - off] : 0; __syncthreads();
        s[t] += x; __syncthreads();
    }
    if (i < n) g_rowptr[i] = s[t] - v;
    if (t == SCAN_BS - 1) g_bsum[blockIdx.x] = s[t];
}
__global__ void scan2_kernel(int nb) {
    __shared__ int s[512];
    int t = threadIdx.x;
    int v = (t < nb) ? g_bsum[t] : 0;
    s[t] = v; __syncthreads();
#pragma unroll
    for (int off = 1; off < 512; off <<= 1) {
        int x = (t >= off) ? s[t - off] : 0; __syncthreads();
        s[t] += x; __syncthreads();
    }
    if (t < nb) g_bsum[t] = s[t] - v;
}
__global__ void scan3_kernel(int n, int E) {
    int i = blockIdx.x * blockDim.x + threadIdx.x;
    if (i < n) {
        int r = g_rowptr[i] + g_bsum[i >> 8];
        g_rowptr[i] = r; g_cursor[i] = r;
    }
    if (i == 0) g_rowptr[n] = E;
}
__global__ void fill_kernel(const int* __restrict__ src,
                            const int* __restrict__ dst, int E) {
    int e = blockIdx.x * blockDim.x + threadIdx.x;
    if (e < E) {
        int pos = atomicAdd(&g_cursor[dst[e]], 1);
        g_esrc[pos] = src[e];
    }
}

// ---------------- SGEMM (FFMA2): g_h = (A * g_ns[:,None]) @ W[128,128] -------
#define BM 128
#define BN 128
#define BK 32
#define APAD (BK + 1)

__global__ __launch_bounds__(256, 2) void gemm_norm_kernel(
    const float* __restrict__ Aext, const float* __restrict__ W, int M) {
    const float* A = Aext ? Aext : g_agg;

    __shared__ float As[BM * APAD];  // [m][k], padded
    __shared__ float Bs[BK * BN];    // [k][n]

    const int tid = threadIdx.x;
    const int tx = tid & 15;   // n block of 8
    const int ty = tid >> 4;   // m block of 8
    const int row0 = blockIdx.x * BM;

    // acc2[i][j] = columns (tx*8 + 2j, tx*8 + 2j + 1) for row ty*8+i
    float2 acc2[8][4];
#pragma unroll
    for (int i = 0; i < 8; i++)
#pragma unroll
        for (int j = 0; j < 4; j++) acc2[i][j] = make_float2(0.f, 0.f);

    for (int k0 = 0; k0 < FD; k0 += BK) {
        // Load A tile (fused norm_src scaling)
#pragma unroll
        for (int i = 0; i < 4; i++) {
            int id = tid + i * 256;
            int r = id >> 3;
            int c4 = id & 7;
            int grow = row0 + r;
            float4 v = make_float4(0.f, 0.f, 0.f, 0.f);
            float nm = 0.f;
            if (grow < M) {
                v = *reinterpret_cast<const float4*>(A + (size_t)grow * FD + k0 + c4 * 4);
                nm = g_ns[grow];
            }
            float* dstp = &As[r * APAD + c4 * 4];
            dstp[0] = v.x * nm; dstp[1] = v.y * nm;
            dstp[2] = v.z * nm; dstp[3] = v.w * nm;
        }
        // Load B tile
#pragma unroll
        for (int i = 0; i < 4; i++) {
            int id = tid + i * 256;
            int r = id >> 5;
            int c4 = id & 31;
            float4 v = *reinterpret_cast<const float4*>(W + (size_t)(k0 + r) * FD + c4 * 4);
            *reinterpret_cast<float4*>(&Bs[r * BN + c4 * 4]) = v;
        }
        __syncthreads();

#pragma unroll
        for (int kk = 0; kk < BK; kk++) {
            float a[8];
#pragma unroll
            for (int i = 0; i < 8; i++) a[i] = As[(ty * 8 + i) * APAD + kk];
            float4 b0 = *reinterpret_cast<const float4*>(&Bs[kk * BN + tx * 8]);
            float4 b1 = *reinterpret_cast<const float4*>(&Bs[kk * BN + tx * 8 + 4]);
            float2 bp[4];
            bp[0] = make_float2(b0.x, b0.y); bp[1] = make_float2(b0.z, b0.w);
            bp[2] = make_float2(b1.x, b1.y); bp[3] = make_float2(b1.z, b1.w);
#pragma unroll
            for (int i = 0; i < 8; i++) {
                float2 aa = dup2(a[i]);
#pragma unroll
                for (int j = 0; j < 4; j++) ffma2(acc2[i][j], aa, bp[j]);
            }
        }
        __syncthreads();
    }

#pragma unroll
    for (int i = 0; i < 8; i++) {
        int grow = row0 + ty * 8 + i;
        if (grow < M) {
            float4* cp = reinterpret_cast<float4*>(g_h + (size_t)grow * FD + tx * 8);
            cp[0] = make_float4(acc2[i][0].x, acc2[i][0].y, acc2[i][1].x, acc2[i][1].y);
            cp[1] = make_float4(acc2[i][2].x, acc2[i][2].y, acc2[i][3].x, acc2[i][3].y);
        }
    }
}

// ---------------- CSR aggregate + fused epilogue ----------------
__global__ __launch_bounds__(256) void agg_kernel(
    const float* __restrict__ bvec, float* __restrict__ out,
    int M, int do_relu) {
    const int warp = (blockIdx.x * blockDim.x + threadIdx.x) >> 5;
    const int lane = threadIdx.x & 31;
    if (warp >= M) return;

    const int beg = __ldg(&g_rowptr[warp]);
    const int end = __ldg(&g_rowptr[warp + 1]);

    float4 acc = make_float4(0.f, 0.f, 0.f, 0.f);
    int j = beg;
    for (; j + 3 < end; j += 4) {
        int s0 = __ldg(&g_esrc[j]);
        int s1 = __ldg(&g_esrc[j + 1]);
        int s2 = __ldg(&g_esrc[j + 2]);
        int s3 = __ldg(&g_esrc[j + 3]);
        float4 v0 = __ldg(reinterpret_cast<const float4*>(g_h + (size_t)s0 * FD) + lane);
        float4 v1 = __ldg(reinterpret_cast<const float4*>(g_h + (size_t)s1 * FD) + lane);
        float4 v2 = __ldg(reinterpret_cast<const float4*>(g_h + (size_t)s2 * FD) + lane);
        float4 v3 = __ldg(reinterpret_cast<const float4*>(g_h + (size_t)s3 * FD) + lane);
        acc.x += (v0.x + v1.x) + (v2.x + v3.x);
        acc.y += (v0.y + v1.y) + (v2.y + v3.y);
        acc.z += (v0.z + v1.z) + (v2.z + v3.z);
        acc.w += (v0.w + v1.w) + (v2.w + v3.w);
    }
    for (; j < end; j++) {
        int s0 = __ldg(&g_esrc[j]);
        float4 v0 = __ldg(reinterpret_cast<const float4*>(g_h + (size_t)s0 * FD) + lane);
        acc.x += v0.x; acc.y += v0.y; acc.z += v0.z; acc.w += v0.w;
    }

    const float nd = g_nd[warp];
    const float4 bb = __ldg(reinterpret_cast<const float4*>(bvec) + lane);
    acc.x = acc.x * nd + bb.x; acc.y = acc.y * nd + bb.y;
    acc.z = acc.z * nd + bb.z; acc.w = acc.w * nd + bb.w;
    if (do_relu) {
        acc.x = fmaxf(acc.x, 0.f); acc.y = fmaxf(acc.y, 0.f);
        acc.z = fmaxf(acc.z, 0.f); acc.w = fmaxf(acc.w, 0.f);
    }
    float* dstrow = out ? out : g_agg;
    reinterpret_cast<float4*>(dstrow + (size_t)warp * FD)[lane] = acc;
}

// ---------------- Launch ----------------
extern "C" void kernel_launch(void* const* d_in, const int* in_sizes, int n_in,
                              void* d_out, int out_size) {
    const float* features = (const float*)d_in[0];
    const int* src = (const int*)d_in[1];
    const int* dst = (const int*)d_in[2];
    const float* W1 = (const float*)d_in[3];
    const float* b1 = (const float*)d_in[4];
    const float* W2 = (const float*)d_in[5];
    const float* b2 = (const float*)d_in[6];
    float* out = (float*)d_out;

    const int M = in_sizes[0] / FD;   // 100000
    const int E = in_sizes[1];        // 1600000

    const int T = 256;
    const int mb = (M + T - 1) / T;
    const int eb = (E + T - 1) / T;

    // Degrees, norms, CSR build
    zero_cnt_kernel<<<mb, T>>>(M);
    degree_kernel<<<eb, T>>>(src, dst, E);
    norm_kernel<<<mb, T>>>(M);
    scan1_kernel<<<NB1, SCAN_BS>>>(M);
    scan2_kernel<<<1, 512>>>(NB1);
    scan3_kernel<<<mb, T>>>(M, E);
    fill_kernel<<<eb, T>>>(src, dst, E);

    const int gemm_blocks = (M + BM - 1) / BM;
    const int agg_blocks = (M * 32 + T - 1) / T;   // one warp per node

    // Layer 1
    gemm_norm_kernel<<<gemm_blocks, 256>>>(features, W1, M);
    agg_kernel<<<agg_blocks, T>>>(b1, nullptr, M, 1);

    // Layer 2
    gemm_norm_kernel<<<gemm_blocks, 256>>>(nullptr, W2, M);
    agg_kernel<<<agg_blocks, T>>>(b2, out, M, 0);
}

// round 6
// speedup vs baseline: 2.4381x; 1.1675x over previous
#include <cuda_runtime.h>
#include <cuda_bf16.h>
#include <cstdint>

// Problem constants
#define NN 100000
#define FD 128
#define NEMAX 1600000
#define SCAN_BS 256
#define NB1 ((NN + SCAN_BS - 1) / SCAN_BS)   // 391

// ---------------- Scratch (static __device__, device-code access only) ------
__device__ float g_h[(size_t)NN * FD];    // GEMM output / messages
__device__ float g_agg[(size_t)NN * FD];  // layer-1 activation
__device__ float g_ns[NN];                // norm_src
__device__ float g_nd[NN];                // norm_dst
__device__ int   g_co[NN];
__device__ int   g_ci[NN];
__device__ int   g_rowptr[NN + 1];
__device__ int   g_cursor[NN];
__device__ int   g_esrc[NEMAX];
__device__ int   g_bsum[NB1];
// Transposed + split weights: [n][k] bf16
__device__ __nv_bfloat16 g_w1hi[FD * FD], g_w1lo[FD * FD];
__device__ __nv_bfloat16 g_w2hi[FD * FD], g_w2lo[FD * FD];

// ---------------- Base-PTX MMA helpers (sm_80-era, safe on compute_103) -----
__device__ __forceinline__ uint32_t smem_u32(const void* p) {
    uint32_t a;
    asm("{ .reg .u64 t; cvta.to.shared.u64 t, %1; cvt.u32.u64 %0, t; }"
        : "=r"(a) : "l"(p));
    return a;
}
#define LDSM4(r0, r1, r2, r3, addr) \
    asm volatile("ldmatrix.sync.aligned.m8n8.x4.shared.b16 {%0,%1,%2,%3}, [%4];" \
                 : "=r"(r0), "=r"(r1), "=r"(r2), "=r"(r3) : "r"(addr))
#define LDSM2(r0, r1, addr) \
    asm volatile("ldmatrix.sync.aligned.m8n8.x2.shared.b16 {%0,%1}, [%2];" \
                 : "=r"(r0), "=r"(r1) : "r"(addr))
__device__ __forceinline__ void mma16816(float* c, const uint32_t* a, const uint32_t* b) {
    asm volatile("mma.sync.aligned.m16n8k16.row.col.f32.bf16.bf16.f32 "
                 "{%0,%1,%2,%3}, {%4,%5,%6,%7}, {%8,%9}, {%0,%1,%2,%3};"
                 : "+f"(c[0]), "+f"(c[1]), "+f"(c[2]), "+f"(c[3])
                 : "r"(a[0]), "r"(a[1]), "r"(a[2]), "r"(a[3]),
                   "r"(b[0]), "r"(b[1]));
}

// ---------------- Degree / norms / CSR build ----------------
__global__ void zero_cnt_kernel(int n) {
    int i = blockIdx.x * blockDim.x + threadIdx.x;
    if (i < n) { g_co[i] = 0; g_ci[i] = 0; }
}
__global__ void degree_kernel(const int* __restrict__ src,
                              const int* __restrict__ dst, int E) {
    int i = blockIdx.x * blockDim.x + threadIdx.x;
    if (i < E) { atomicAdd(&g_co[src[i]], 1); atomicAdd(&g_ci[dst[i]], 1); }
}
__global__ void norm_kernel(int n) {
    int i = blockIdx.x * blockDim.x + threadIdx.x;
    if (i < n) {
        g_ns[i] = rsqrtf(fmaxf((float)g_co[i], 1.f));
        g_nd[i] = rsqrtf(fmaxf((float)g_ci[i], 1.f));
    }
}
__global__ void scan1_kernel(int n) {
    __shared__ int s[SCAN_BS];
    int t = threadIdx.x, i = blockIdx.x * SCAN_BS + t;
    int v = (i < n) ? g_ci[i] : 0;
    s[t] = v; __syncthreads();
#pragma unroll
    for (int off = 1; off < SCAN_BS; off <<= 1) {
        int x = (t >= off) ? s[t - off] : 0; __syncthreads();
        s[t] += x; __syncthreads();
    }
    if (i < n) g_rowptr[i] = s[t] - v;
    if (t == SCAN_BS - 1) g_bsum[blockIdx.x] = s[t];
}
__global__ void scan2_kernel(int nb) {
    __shared__ int s[512];
    int t = threadIdx.x;
    int v = (t < nb) ? g_bsum[t] : 0;
    s[t] = v; __syncthreads();
#pragma unroll
    for (int off = 1; off < 512; off <<= 1) {
        int x = (t >= off) ? s[t - off] : 0; __syncthreads();
        s[t] += x; __syncthreads();
    }
    if (t < nb) g_bsum[t] = s[t] - v;
}
__global__ void scan3_kernel(int n, int E) {
    int i = blockIdx.x * blockDim.x + threadIdx.x;
    if (i < n) {
        int r = g_rowptr[i] + g_bsum[i >> 8];
        g_rowptr[i] = r; g_cursor[i] = r;
    }
    if (i == 0) g_rowptr[n] = E;
}
__global__ void fill_kernel(const int* __restrict__ src,
                            const int* __restrict__ dst, int E) {
    int e = blockIdx.x * blockDim.x + threadIdx.x;
    if (e < E) {
        int pos = atomicAdd(&g_cursor[dst[e]], 1);
        g_esrc[pos] = src[e];
    }
}

// ---------------- Weight prep: transpose + bf16 split ----------------
__global__ void prep_w_kernel(const float* __restrict__ W1,
                              const float* __restrict__ W2) {
    int i = blockIdx.x * blockDim.x + threadIdx.x;
    if (i < FD * FD) {
        int k = i >> 7, n = i & 127;
        float w = W1[i];
        __nv_bfloat16 h = __float2bfloat16(w);
        g_w1hi[n * FD + k] = h;
        g_w1lo[n * FD + k] = __float2bfloat16(w - __bfloat162float(h));
        w = W2[i];
        h = __float2bfloat16(w);
        g_w2hi[n * FD + k] = h;
        g_w2lo[n * FD + k] = __float2bfloat16(w - __bfloat162float(h));
    }
}

// ---------------- mma.sync GEMM: g_h = (A * ns) @ W  (split-bf16, f32 acc) ---
// Block tile 128x128, K=128 all-resident. 256 threads = 8 warps (2x4),
// warp tile 64x32. SMEM rows padded to 136 bf16 for conflict-free LDSM.
#define ASTRIDE 136
#define TILE_B (128 * ASTRIDE * 2)   // 34816 bytes
#define OFF_AH 0
#define OFF_AL TILE_B
#define OFF_BH (2 * TILE_B)
#define OFF_BL (3 * TILE_B)
#define GEMM_SMEM (4 * TILE_B)       // 139264 bytes

__global__ __launch_bounds__(256) void gemm_mma_kernel(
    const float* __restrict__ Aext, int layer, int M) {
    extern __shared__ char sm[];
    const uint32_t sb = smem_u32(sm);
    const int tid = threadIdx.x;
    const int lane = tid & 31;
    const int wid = tid >> 5;
    const int row0 = blockIdx.x * 128;
    const float* A = Aext ? Aext : g_agg;

    // ---- Fill A_hi/A_lo: thread handles row tid/2, 64-col half ----
    {
        int r = tid >> 1;
        int cs = (tid & 1) * 64;
        int grow = row0 + r;
        uint32_t base = (uint32_t)(r * ASTRIDE + cs) * 2;
        if (grow < M) {
            float nm = g_ns[grow];
            const float4* ap = reinterpret_cast<const float4*>(A + (size_t)grow * FD + cs);
#pragma unroll
            for (int j = 0; j < 16; j++) {
                float4 v = __ldg(&ap[j]);
                float x0 = v.x * nm, x1 = v.y * nm, x2 = v.z * nm, x3 = v.w * nm;
                __nv_bfloat16 h0 = __float2bfloat16(x0), h1 = __float2bfloat16(x1);
                __nv_bfloat16 h2 = __float2bfloat16(x2), h3 = __float2bfloat16(x3);
                __nv_bfloat162 hp0 = __halves2bfloat162(h0, h1);
                __nv_bfloat162 hp1 = __halves2bfloat162(h2, h3);
                __nv_bfloat162 lp0 = __floats2bfloat162_rn(x0 - __bfloat162float(h0),
                                                           x1 - __bfloat162float(h1));
                __nv_bfloat162 lp1 = __floats2bfloat162_rn(x2 - __bfloat162float(h2),
                                                           x3 - __bfloat162float(h3));
                uint32_t o = base + j * 8;
                *reinterpret_cast<uint32_t*>(sm + OFF_AH + o)     = *reinterpret_cast<uint32_t*>(&hp0);
                *reinterpret_cast<uint32_t*>(sm + OFF_AH + o + 4) = *reinterpret_cast<uint32_t*>(&hp1);
                *reinterpret_cast<uint32_t*>(sm + OFF_AL + o)     = *reinterpret_cast<uint32_t*>(&lp0);
                *reinterpret_cast<uint32_t*>(sm + OFF_AL + o + 4) = *reinterpret_cast<uint32_t*>(&lp1);
            }
        } else {
#pragma unroll
            for (int j = 0; j < 16; j++) {
                uint32_t o = base + j * 8;
                *reinterpret_cast<uint32_t*>(sm + OFF_AH + o)     = 0u;
                *reinterpret_cast<uint32_t*>(sm + OFF_AH + o + 4) = 0u;
                *reinterpret_cast<uint32_t*>(sm + OFF_AL + o)     = 0u;
                *reinterpret_cast<uint32_t*>(sm + OFF_AL + o + 4) = 0u;
            }
        }
    }
    // ---- Fill B_hi/B_lo from pre-split [n][k] weights ----
    {
        const __nv_bfloat16* whi = (layer == 1) ? g_w1hi : g_w2hi;
        const __nv_bfloat16* wlo = (layer == 1) ? g_w1lo : g_w2lo;
        int n = tid >> 1;
        int cs = (tid & 1) * 64;
        uint32_t base = (uint32_t)(n * ASTRIDE + cs) * 2;
        const uint4* ph = reinterpret_cast<const uint4*>(whi + (size_t)n * FD + cs);
        const uint4* pl = reinterpret_cast<const uint4*>(wlo + (size_t)n * FD + cs);
#pragma unroll
        for (int j = 0; j < 8; j++) {   // 8 bf16 per uint4
            *reinterpret_cast<uint4*>(sm + OFF_BH + base + j * 16) = __ldg(&ph[j]);
            *reinterpret_cast<uint4*>(sm + OFF_BL + base + j * 16) = __ldg(&pl[j]);
        }
    }
    __syncthreads();

    // ---- Mainloop ----
    const int m0 = (wid >> 2) * 64;      // warp row origin
    const int n0 = (wid & 3) * 32;       // warp col origin

    float acc[4][4][4];
#pragma unroll
    for (int mi = 0; mi < 4; mi++)
#pragma unroll
        for (int ni = 0; ni < 4; ni++)
#pragma unroll
            for (int q = 0; q < 4; q++) acc[mi][ni][q] = 0.f;

    // lane addressing for LDSM (byte offsets within a tile)
    const uint32_t aOff = (uint32_t)((m0 + (lane & 15)) * ASTRIDE + ((lane >> 4) << 3)) * 2;
    const uint32_t bOff = (uint32_t)((n0 + (lane & 7)) * ASTRIDE + (((lane >> 3) & 1) << 3)) * 2;
    const uint32_t aHi = sb + OFF_AH + aOff, aLo = sb + OFF_AL + aOff;
    const uint32_t bHi = sb + OFF_BH + bOff, bLo = sb + OFF_BL + bOff;

#pragma unroll 2
    for (int ks = 0; ks < 8; ks++) {
        const uint32_t ka = ks * 32;     // 16 bf16 = 32 bytes per k-step
        uint32_t ah[4][4], al[4][4], bh[4][2], bl[4][2];
#pragma unroll
        for (int mi = 0; mi < 4; mi++) {
            LDSM4(ah[mi][0], ah[mi][1], ah[mi][2], ah[mi][3], aHi + mi * (16 * ASTRIDE * 2) + ka);
            LDSM4(al[mi][0], al[mi][1], al[mi][2], al[mi][3], aLo + mi * (16 * ASTRIDE * 2) + ka);
        }
#pragma unroll
        for (int ni = 0; ni < 4; ni++) {
            LDSM2(bh[ni][0], bh[ni][1], bHi + ni * (8 * ASTRIDE * 2) + ka);
            LDSM2(bl[ni][0], bl[ni][1], bLo + ni * (8 * ASTRIDE * 2) + ka);
        }
#pragma unroll
        for (int mi = 0; mi < 4; mi++)
#pragma unroll
            for (int ni = 0; ni < 4; ni++) {
                mma16816(acc[mi][ni], ah[mi], bh[ni]);  // hi*hi
                mma16816(acc[mi][ni], ah[mi], bl[ni]);  // hi*lo
                mma16816(acc[mi][ni], al[mi], bh[ni]);  // lo*hi
            }
    }

    // ---- Epilogue: fragment -> g_h ----
    const int rb = m0 + (lane >> 2);
    const int cb = n0 + (lane & 3) * 2;
#pragma unroll
    for (int mi = 0; mi < 4; mi++) {
        int r0g = row0 + rb + mi * 16;
#pragma unroll
        for (int ni = 0; ni < 4; ni++) {
            int col = cb + ni * 8;
            if (r0g < M)
                *reinterpret_cast<float2*>(g_h + (size_t)r0g * FD + col) =
                    make_float2(acc[mi][ni][0], acc[mi][ni][1]);
            if (r0g + 8 < M)
                *reinterpret_cast<float2*>(g_h + (size_t)(r0g + 8) * FD + col) =
                    make_float2(acc[mi][ni][2], acc[mi][ni][3]);
        }
    }
}

// ---------------- CSR aggregate + fused epilogue ----------------
__global__ __launch_bounds__(256) void agg_kernel(
    const float* __restrict__ bvec, float* __restrict__ out,
    int M, int do_relu) {
    const int warp = (blockIdx.x * blockDim.x + threadIdx.x) >> 5;
    const int lane = threadIdx.x & 31;
    if (warp >= M) return;

    const int beg = __ldg(&g_rowptr[warp]);
    const int end = __ldg(&g_rowptr[warp + 1]);

    float4 acc = make_float4(0.f, 0.f, 0.f, 0.f);
    int j = beg;
    for (; j + 3 < end; j += 4) {
        int s0 = __ldg(&g_esrc[j]);
        int s1 = __ldg(&g_esrc[j + 1]);
        int s2 = __ldg(&g_esrc[j + 2]);
        int s3 = __ldg(&g_esrc[j + 3]);
        float4 v0 = __ldg(reinterpret_cast<const float4*>(g_h + (size_t)s0 * FD) + lane);
        float4 v1 = __ldg(reinterpret_cast<const float4*>(g_h + (size_t)s1 * FD) + lane);
        float4 v2 = __ldg(reinterpret_cast<const float4*>(g_h + (size_t)s2 * FD) + lane);
        float4 v3 = __ldg(reinterpret_cast<const float4*>(g_h + (size_t)s3 * FD) + lane);
        acc.x += (v0.x + v1.x) + (v2.x + v3.x);
        acc.y += (v0.y + v1.y) + (v2.y + v3.y);
        acc.z += (v0.z + v1.z) + (v2.z + v3.z);
        acc.w += (v0.w + v1.w) + (v2.w + v3.w);
    }
    for (; j < end; j++) {
        int s0 = __ldg(&g_esrc[j]);
        float4 v0 = __ldg(reinterpret_cast<const float4*>(g_h + (size_t)s0 * FD) + lane);
        acc.x += v0.x; acc.y += v0.y; acc.z += v0.z; acc.w += v0.w;
    }

    const float nd = g_nd[warp];
    const float4 bb = __ldg(reinterpret_cast<const float4*>(bvec) + lane);
    acc.x = acc.x * nd + bb.x; acc.y = acc.y * nd + bb.y;
    acc.z = acc.z * nd + bb.z; acc.w = acc.w * nd + bb.w;
    if (do_relu) {
        acc.x = fmaxf(acc.x, 0.f); acc.y = fmaxf(acc.y, 0.f);
        acc.z = fmaxf(acc.z, 0.f); acc.w = fmaxf(acc.w, 0.f);
    }
    float* dstrow = out ? out : g_agg;
    reinterpret_cast<float4*>(dstrow + (size_t)warp * FD)[lane] = acc;
}

// ---------------- Launch ----------------
extern "C" void kernel_launch(void* const* d_in, const int* in_sizes, int n_in,
                              void* d_out, int out_size) {
    const float* features = (const float*)d_in[0];
    const int* src = (const int*)d_in[1];
    const int* dst = (const int*)d_in[2];
    const float* W1 = (const float*)d_in[3];
    const float* b1 = (const float*)d_in[4];
    const float* W2 = (const float*)d_in[5];
    const float* b2 = (const float*)d_in[6];
    float* out = (float*)d_out;

    const int M = in_sizes[0] / FD;   // 100000
    const int E = in_sizes[1];        // 1600000

    cudaFuncSetAttribute(gemm_mma_kernel,
                         cudaFuncAttributeMaxDynamicSharedMemorySize, GEMM_SMEM);

    const int T = 256;
    const int mb = (M + T - 1) / T;
    const int eb = (E + T - 1) / T;

    // Degrees, norms, CSR build, weight prep
    zero_cnt_kernel<<<mb, T>>>(M);
    degree_kernel<<<eb, T>>>(src, dst, E);
    norm_kernel<<<mb, T>>>(M);
    scan1_kernel<<<NB1, SCAN_BS>>>(M);
    scan2_kernel<<<1, 512>>>(NB1);
    scan3_kernel<<<mb, T>>>(M, E);
    fill_kernel<<<eb, T>>>(src, dst, E);
    prep_w_kernel<<<(FD * FD + T - 1) / T, T>>>(W1, W2);

    const int gemm_blocks = (M + 127) / 128;        // 782
    const int agg_blocks = (M * 32 + T - 1) / T;    // one warp per node

    // Layer 1
    gemm_mma_kernel<<<gemm_blocks, 256, GEMM_SMEM>>>(features, 1, M);
    agg_kernel<<<agg_blocks, T>>>(b1, nullptr, M, 1);

    // Layer 2
    gemm_mma_kernel<<<gemm_blocks, 256, GEMM_SMEM>>>(nullptr, 2, M);
    agg_kernel<<<agg_blocks, T>>>(b2, out, M, 0);
}

// round 7
// speedup vs baseline: 2.8255x; 1.1589x over previous
#include <cuda_runtime.h>
#include <cuda_bf16.h>
#include <cuda_fp16.h>
#include <cstdint>

// Problem constants
#define NN 100000
#define FD 128
#define NEMAX 1600000
#define SCAN_BS 256
#define NB1 ((NN + SCAN_BS - 1) / SCAN_BS)   // 391

// ---------------- Scratch (static __device__, device-code access only) ------
__device__ __half g_hh[(size_t)NN * FD];  // GEMM output / messages (fp16, 25.6 MB)
__device__ float g_agg[(size_t)NN * FD];  // layer-1 activation (fp32)
__device__ float g_ns[NN];                // norm_src
__device__ float g_nd[NN];                // norm_dst
__device__ int   g_co[NN];
__device__ int   g_ci[NN];
__device__ int   g_rowptr[NN + 1];
__device__ int   g_cursor[NN];
__device__ int   g_esrc[NEMAX];
__device__ int   g_bsum[NB1];
// Transposed + split weights: [n][k] bf16
__device__ __nv_bfloat16 g_w1hi[FD * FD], g_w1lo[FD * FD];
__device__ __nv_bfloat16 g_w2hi[FD * FD], g_w2lo[FD * FD];

// ---------------- Base-PTX MMA helpers ----------------
__device__ __forceinline__ uint32_t smem_u32(const void* p) {
    uint32_t a;
    asm("{ .reg .u64 t; cvta.to.shared.u64 t, %1; cvt.u32.u64 %0, t; }"
        : "=r"(a) : "l"(p));
    return a;
}
#define LDSM4(r0, r1, r2, r3, addr) \
    asm volatile("ldmatrix.sync.aligned.m8n8.x4.shared.b16 {%0,%1,%2,%3}, [%4];" \
                 : "=r"(r0), "=r"(r1), "=r"(r2), "=r"(r3) : "r"(addr))
#define LDSM2(r0, r1, addr) \
    asm volatile("ldmatrix.sync.aligned.m8n8.x2.shared.b16 {%0,%1}, [%2];" \
                 : "=r"(r0), "=r"(r1) : "r"(addr))
__device__ __forceinline__ void mma16816(float* c, const uint32_t* a, const uint32_t* b) {
    asm volatile("mma.sync.aligned.m16n8k16.row.col.f32.bf16.bf16.f32 "
                 "{%0,%1,%2,%3}, {%4,%5,%6,%7}, {%8,%9}, {%0,%1,%2,%3};"
                 : "+f"(c[0]), "+f"(c[1]), "+f"(c[2]), "+f"(c[3])
                 : "r"(a[0]), "r"(a[1]), "r"(a[2]), "r"(a[3]),
                   "r"(b[0]), "r"(b[1]));
}

// ---------------- Degree / norms / CSR build ----------------
__global__ void zero_cnt_kernel(int n) {
    int i = blockIdx.x * blockDim.x + threadIdx.x;
    if (i < n) { g_co[i] = 0; g_ci[i] = 0; }
}
__global__ void degree_kernel(const int* __restrict__ src,
                              const int* __restrict__ dst, int E) {
    int i = blockIdx.x * blockDim.x + threadIdx.x;
    if (i < E) { atomicAdd(&g_co[src[i]], 1); atomicAdd(&g_ci[dst[i]], 1); }
}
__global__ void norm_kernel(int n) {
    int i = blockIdx.x * blockDim.x + threadIdx.x;
    if (i < n) {
        g_ns[i] = rsqrtf(fmaxf((float)g_co[i], 1.f));
        g_nd[i] = rsqrtf(fmaxf((float)g_ci[i], 1.f));
    }
}
__global__ void scan1_kernel(int n) {
    __shared__ int s[SCAN_BS];
    int t = threadIdx.x, i = blockIdx.x * SCAN_BS + t;
    int v = (i < n) ? g_ci[i] : 0;
    s[t] = v; __syncthreads();
#pragma unroll
    for (int off = 1; off < SCAN_BS; off <<= 1) {
        int x = (t >= off) ? s[t - off] : 0; __syncthreads();
        s[t] += x; __syncthreads();
    }
    if (i < n) g_rowptr[i] = s[t] - v;
    if (t == SCAN_BS - 1) g_bsum[blockIdx.x] = s[t];
}
__global__ void scan2_kernel(int nb) {
    __shared__ int s[512];
    int t = threadIdx.x;
    int v = (t < nb) ? g_bsum[t] : 0;
    s[t] = v; __syncthreads();
#pragma unroll
    for (int off = 1; off < 512; off <<= 1) {
        int x = (t >= off) ? s[t - off] : 0; __syncthreads();
        s[t] += x; __syncthreads();
    }
    if (t < nb) g_bsum[t] = s[t] - v;
}
__global__ void scan3_kernel(int n, int E) {
    int i = blockIdx.x * blockDim.x + threadIdx.x;
    if (i < n) {
        int r = g_rowptr[i] + g_bsum[i >> 8];
        g_rowptr[i] = r; g_cursor[i] = r;
    }
    if (i == 0) g_rowptr[n] = E;
}
__global__ void fill_kernel(const int* __restrict__ src,
                            const int* __restrict__ dst, int E) {
    int e = blockIdx.x * blockDim.x + threadIdx.x;
    if (e < E) {
        int pos = atomicAdd(&g_cursor[dst[e]], 1);
        g_esrc[pos] = src[e];
    }
}

// ---------------- Weight prep: transpose + bf16 split ----------------
__global__ void prep_w_kernel(const float* __restrict__ W1,
                              const float* __restrict__ W2) {
    int i = blockIdx.x * blockDim.x + threadIdx.x;
    if (i < FD * FD) {
        int k = i >> 7, n = i & 127;
        float w = W1[i];
        __nv_bfloat16 h = __float2bfloat16(w);
        g_w1hi[n * FD + k] = h;
        g_w1lo[n * FD + k] = __float2bfloat16(w - __bfloat162float(h));
        w = W2[i];
        h = __float2bfloat16(w);
        g_w2hi[n * FD + k] = h;
        g_w2lo[n * FD + k] = __float2bfloat16(w - __bfloat162float(h));
    }
}

// ---------------- mma.sync GEMM: g_hh = fp16((A * ns) @ W) -------------------
#define ASTRIDE 136
#define TILE_B (128 * ASTRIDE * 2)   // 34816 bytes
#define OFF_AH 0
#define OFF_AL TILE_B
#define OFF_BH (2 * TILE_B)
#define OFF_BL (3 * TILE_B)
#define GEMM_SMEM (4 * TILE_B)       // 139264 bytes

__global__ __launch_bounds__(256) void gemm_mma_kernel(
    const float* __restrict__ Aext, int layer, int M) {
    extern __shared__ char sm[];
    const uint32_t sb = smem_u32(sm);
    const int tid = threadIdx.x;
    const int lane = tid & 31;
    const int wid = tid >> 5;
    const int row0 = blockIdx.x * 128;
    const float* A = Aext ? Aext : g_agg;

    // ---- Fill A_hi/A_lo: thread handles row tid/2, 64-col half ----
    {
        int r = tid >> 1;
        int cs = (tid & 1) * 64;
        int grow = row0 + r;
        uint32_t base = (uint32_t)(r * ASTRIDE + cs) * 2;
        if (grow < M) {
            float nm = g_ns[grow];
            const float4* ap = reinterpret_cast<const float4*>(A + (size_t)grow * FD + cs);
#pragma unroll
            for (int j = 0; j < 16; j++) {
                float4 v = __ldg(&ap[j]);
                float x0 = v.x * nm, x1 = v.y * nm, x2 = v.z * nm, x3 = v.w * nm;
                __nv_bfloat16 h0 = __float2bfloat16(x0), h1 = __float2bfloat16(x1);
                __nv_bfloat16 h2 = __float2bfloat16(x2), h3 = __float2bfloat16(x3);
                __nv_bfloat162 hp0 = __halves2bfloat162(h0, h1);
                __nv_bfloat162 hp1 = __halves2bfloat162(h2, h3);
                __nv_bfloat162 lp0 = __floats2bfloat162_rn(x0 - __bfloat162float(h0),
                                                           x1 - __bfloat162float(h1));
                __nv_bfloat162 lp1 = __floats2bfloat162_rn(x2 - __bfloat162float(h2),
                                                           x3 - __bfloat162float(h3));
                uint32_t o = base + j * 8;
                *reinterpret_cast<uint32_t*>(sm + OFF_AH + o)     = *reinterpret_cast<uint32_t*>(&hp0);
                *reinterpret_cast<uint32_t*>(sm + OFF_AH + o + 4) = *reinterpret_cast<uint32_t*>(&hp1);
                *reinterpret_cast<uint32_t*>(sm + OFF_AL + o)     = *reinterpret_cast<uint32_t*>(&lp0);
                *reinterpret_cast<uint32_t*>(sm + OFF_AL + o + 4) = *reinterpret_cast<uint32_t*>(&lp1);
            }
        } else {
#pragma unroll
            for (int j = 0; j < 16; j++) {
                uint32_t o = base + j * 8;
                *reinterpret_cast<uint32_t*>(sm + OFF_AH + o)     = 0u;
                *reinterpret_cast<uint32_t*>(sm + OFF_AH + o + 4) = 0u;
                *reinterpret_cast<uint32_t*>(sm + OFF_AL + o)     = 0u;
                *reinterpret_cast<uint32_t*>(sm + OFF_AL + o + 4) = 0u;
            }
        }
    }
    // ---- Fill B_hi/B_lo from pre-split [n][k] weights ----
    {
        const __nv_bfloat16* whi = (layer == 1) ? g_w1hi : g_w2hi;
        const __nv_bfloat16* wlo = (layer == 1) ? g_w1lo : g_w2lo;
        int n = tid >> 1;
        int cs = (tid & 1) * 64;
        uint32_t base = (uint32_t)(n * ASTRIDE + cs) * 2;
        const uint4* ph = reinterpret_cast<const uint4*>(whi + (size_t)n * FD + cs);
        const uint4* pl = reinterpret_cast<const uint4*>(wlo + (size_t)n * FD + cs);
#pragma unroll
        for (int j = 0; j < 8; j++) {
            *reinterpret_cast<uint4*>(sm + OFF_BH + base + j * 16) = __ldg(&ph[j]);
            *reinterpret_cast<uint4*>(sm + OFF_BL + base + j * 16) = __ldg(&pl[j]);
        }
    }
    __syncthreads();

    // ---- Mainloop ----
    const int m0 = (wid >> 2) * 64;
    const int n0 = (wid & 3) * 32;

    float acc[4][4][4];
#pragma unroll
    for (int mi = 0; mi < 4; mi++)
#pragma unroll
        for (int ni = 0; ni < 4; ni++)
#pragma unroll
            for (int q = 0; q < 4; q++) acc[mi][ni][q] = 0.f;

    const uint32_t aOff = (uint32_t)((m0 + (lane & 15)) * ASTRIDE + ((lane >> 4) << 3)) * 2;
    const uint32_t bOff = (uint32_t)((n0 + (lane & 7)) * ASTRIDE + (((lane >> 3) & 1) << 3)) * 2;
    const uint32_t aHi = sb + OFF_AH + aOff, aLo = sb + OFF_AL + aOff;
    const uint32_t bHi = sb + OFF_BH + bOff, bLo = sb + OFF_BL + bOff;

#pragma unroll 2
    for (int ks = 0; ks < 8; ks++) {
        const uint32_t ka = ks * 32;
        uint32_t ah[4][4], al[4][4], bh[4][2], bl[4][2];
#pragma unroll
        for (int mi = 0; mi < 4; mi++) {
            LDSM4(ah[mi][0], ah[mi][1], ah[mi][2], ah[mi][3], aHi + mi * (16 * ASTRIDE * 2) + ka);
            LDSM4(al[mi][0], al[mi][1], al[mi][2], al[mi][3], aLo + mi * (16 * ASTRIDE * 2) + ka);
        }
#pragma unroll
        for (int ni = 0; ni < 4; ni++) {
            LDSM2(bh[ni][0], bh[ni][1], bHi + ni * (8 * ASTRIDE * 2) + ka);
            LDSM2(bl[ni][0], bl[ni][1], bLo + ni * (8 * ASTRIDE * 2) + ka);
        }
#pragma unroll
        for (int mi = 0; mi < 4; mi++)
#pragma unroll
            for (int ni = 0; ni < 4; ni++) {
                mma16816(acc[mi][ni], ah[mi], bh[ni]);
                mma16816(acc[mi][ni], ah[mi], bl[ni]);
                mma16816(acc[mi][ni], al[mi], bh[ni]);
            }
    }

    // ---- Epilogue: fragment -> g_hh (fp16) ----
    const int rb = m0 + (lane >> 2);
    const int cb = n0 + (lane & 3) * 2;
#pragma unroll
    for (int mi = 0; mi < 4; mi++) {
        int r0g = row0 + rb + mi * 16;
#pragma unroll
        for (int ni = 0; ni < 4; ni++) {
            int col = cb + ni * 8;
            if (r0g < M)
                *reinterpret_cast<__half2*>(g_hh + (size_t)r0g * FD + col) =
                    __floats2half2_rn(acc[mi][ni][0], acc[mi][ni][1]);
            if (r0g + 8 < M)
                *reinterpret_cast<__half2*>(g_hh + (size_t)(r0g + 8) * FD + col) =
                    __floats2half2_rn(acc[mi][ni][2], acc[mi][ni][3]);
        }
    }
}

// ---------------- CSR aggregate (fp16 messages) + fused epilogue -------------
__global__ __launch_bounds__(256) void agg_kernel(
    const float* __restrict__ bvec, float* __restrict__ out,
    int M, int do_relu) {
    const int warp = (blockIdx.x * blockDim.x + threadIdx.x) >> 5;
    const int lane = threadIdx.x & 31;
    if (warp >= M) return;

    const int beg = __ldg(&g_rowptr[warp]);
    const int end = __ldg(&g_rowptr[warp + 1]);

    // lane covers features [lane*4, lane*4+3]; row = 128 halves = 32 x uint2
    float4 acc = make_float4(0.f, 0.f, 0.f, 0.f);
    int j = beg;
    for (; j + 3 < end; j += 4) {
        int s0 = __ldg(&g_esrc[j]);
        int s1 = __ldg(&g_esrc[j + 1]);
        int s2 = __ldg(&g_esrc[j + 2]);
        int s3 = __ldg(&g_esrc[j + 3]);
        uint2 u0 = __ldg(reinterpret_cast<const uint2*>(g_hh + (size_t)s0 * FD) + lane);
        uint2 u1 = __ldg(reinterpret_cast<const uint2*>(g_hh + (size_t)s1 * FD) + lane);
        uint2 u2 = __ldg(reinterpret_cast<const uint2*>(g_hh + (size_t)s2 * FD) + lane);
        uint2 u3 = __ldg(reinterpret_cast<const uint2*>(g_hh + (size_t)s3 * FD) + lane);
#pragma unroll
        for (int q = 0; q < 4; q++) {
            uint2 u = (q == 0) ? u0 : (q == 1) ? u1 : (q == 2) ? u2 : u3;
            float2 fa = __half22float2(*reinterpret_cast<__half2*>(&u.x));
            float2 fb = __half22float2(*reinterpret_cast<__half2*>(&u.y));
            acc.x += fa.x; acc.y += fa.y; acc.z += fb.x; acc.w += fb.y;
        }
    }
    for (; j < end; j++) {
        int s0 = __ldg(&g_esrc[j]);
        uint2 u = __ldg(reinterpret_cast<const uint2*>(g_hh + (size_t)s0 * FD) + lane);
        float2 fa = __half22float2(*reinterpret_cast<__half2*>(&u.x));
        float2 fb = __half22float2(*reinterpret_cast<__half2*>(&u.y));
        acc.x += fa.x; acc.y += fa.y; acc.z += fb.x; acc.w += fb.y;
    }

    const float nd = g_nd[warp];
    const float4 bb = __ldg(reinterpret_cast<const float4*>(bvec) + lane);
    acc.x = acc.x * nd + bb.x; acc.y = acc.y * nd + bb.y;
    acc.z = acc.z * nd + bb.z; acc.w = acc.w * nd + bb.w;
    if (do_relu) {
        acc.x = fmaxf(acc.x, 0.f); acc.y = fmaxf(acc.y, 0.f);
        acc.z = fmaxf(acc.z, 0.f); acc.w = fmaxf(acc.w, 0.f);
    }
    float* dstrow = out ? out : g_agg;
    reinterpret_cast<float4*>(dstrow + (size_t)warp * FD)[lane] = acc;
}

// ---------------- Launch ----------------
extern "C" void kernel_launch(void* const* d_in, const int* in_sizes, int n_in,
                              void* d_out, int out_size) {
    const float* features = (const float*)d_in[0];
    const int* src = (const int*)d_in[1];
    const int* dst = (const int*)d_in[2];
    const float* W1 = (const float*)d_in[3];
    const float* b1 = (const float*)d_in[4];
    const float* W2 = (const float*)d_in[5];
    const float* b2 = (const float*)d_in[6];
    float* out = (float*)d_out;

    const int M = in_sizes[0] / FD;   // 100000
    const int E = in_sizes[1];        // 1600000

    // One-time resource setup (host objects only; no device memory)
    static cudaStream_t s2 = nullptr;
    static cudaEvent_t evA = nullptr, evB = nullptr;
    if (!s2) {
        cudaStreamCreateWithFlags(&s2, cudaStreamNonBlocking);
        cudaEventCreateWithFlags(&evA, cudaEventDisableTiming);
        cudaEventCreateWithFlags(&evB, cudaEventDisableTiming);
        cudaFuncSetAttribute(gemm_mma_kernel,
                             cudaFuncAttributeMaxDynamicSharedMemorySize, GEMM_SMEM);
    }

    const int T = 256;
    const int mb = (M + T - 1) / T;
    const int eb = (E + T - 1) / T;

    // Legacy stream: degrees (needed by both branches)
    zero_cnt_kernel<<<mb, T>>>(M);
    degree_kernel<<<eb, T>>>(src, dst, E);
    cudaEventRecord(evA, (cudaStream_t)0);

    // Fork: CSR build on s2, concurrent with norm+prep+gemm1
    cudaStreamWaitEvent(s2, evA, 0);
    scan1_kernel<<<NB1, SCAN_BS, 0, s2>>>(M);
    scan2_kernel<<<1, 512, 0, s2>>>(NB1);
    scan3_kernel<<<mb, T, 0, s2>>>(M, E);
    fill_kernel<<<eb, T, 0, s2>>>(src, dst, E);
    cudaEventRecord(evB, s2);

    // Legacy stream: norms, weight prep, layer-1 GEMM
    norm_kernel<<<mb, T>>>(M);
    prep_w_kernel<<<(FD * FD + T - 1) / T, T>>>(W1, W2);

    const int gemm_blocks = (M + 127) / 128;        // 782
    const int agg_blocks = (M * 32 + T - 1) / T;    // one warp per node

    gemm_mma_kernel<<<gemm_blocks, 256, GEMM_SMEM>>>(features, 1, M);

    // Join: agg1 needs the CSR
    cudaStreamWaitEvent((cudaStream_t)0, evB, 0);
    agg_kernel<<<agg_blocks, T>>>(b1, nullptr, M, 1);

    // Layer 2
    gemm_mma_kernel<<<gemm_blocks, 256, GEMM_SMEM>>>(nullptr, 2, M);
    agg_kernel<<<agg_blocks, T>>>(b2, out, M, 0);
}

// round 8
// speedup vs baseline: 3.7327x; 1.3211x over previous
#include <cuda_runtime.h>
#include <cuda_bf16.h>
#include <cuda_fp16.h>
#include <cstdint>

// Problem constants
#define NN 100000
#define FD 128
#define NEMAX 1600000
#define SCAN_BS 256
#define NB1 ((NN + SCAN_BS - 1) / SCAN_BS)   // 391

// ---------------- Scratch (static __device__, device-code access only) ------
__device__ __half g_hh[(size_t)NN * FD];    // GEMM output / messages (fp16)
__device__ __half g_aggh[(size_t)NN * FD];  // layer-1 activation * ns (fp16)
__device__ float g_ns[NN];                  // norm_src
__device__ float g_nd[NN];                  // norm_dst
__device__ int   g_co[NN];
__device__ int   g_ci[NN];
__device__ int   g_rowptr[NN + 1];
__device__ int   g_cursor[NN];
__device__ int   g_esrc[NEMAX];
__device__ int   g_bsum[NB1];
// Transposed fp16 weights: [n][k]
__device__ __half g_w1h[FD * FD];
__device__ __half g_w2h[FD * FD];

// ---------------- Base-PTX MMA helpers ----------------
__device__ __forceinline__ uint32_t smem_u32(const void* p) {
    uint32_t a;
    asm("{ .reg .u64 t; cvta.to.shared.u64 t, %1; cvt.u32.u64 %0, t; }"
        : "=r"(a) : "l"(p));
    return a;
}
#define LDSM4(r0, r1, r2, r3, addr) \
    asm volatile("ldmatrix.sync.aligned.m8n8.x4.shared.b16 {%0,%1,%2,%3}, [%4];" \
                 : "=r"(r0), "=r"(r1), "=r"(r2), "=r"(r3) : "r"(addr))
#define LDSM2(r0, r1, addr) \
    asm volatile("ldmatrix.sync.aligned.m8n8.x2.shared.b16 {%0,%1}, [%2];" \
                 : "=r"(r0), "=r"(r1) : "r"(addr))
__device__ __forceinline__ void mma16816(float* c, const uint32_t* a, const uint32_t* b) {
    asm volatile("mma.sync.aligned.m16n8k16.row.col.f32.f16.f16.f32 "
                 "{%0,%1,%2,%3}, {%4,%5,%6,%7}, {%8,%9}, {%0,%1,%2,%3};"
                 : "+f"(c[0]), "+f"(c[1]), "+f"(c[2]), "+f"(c[3])
                 : "r"(a[0]), "r"(a[1]), "r"(a[2]), "r"(a[3]),
                   "r"(b[0]), "r"(b[1]));
}

// ---------------- Degree / norms / CSR build ----------------
__global__ void zero_cnt_kernel(int n) {
    int i = blockIdx.x * blockDim.x + threadIdx.x;
    if (i < n) { g_co[i] = 0; g_ci[i] = 0; }
}
__global__ void degree_kernel(const int* __restrict__ src,
                              const int* __restrict__ dst, int E) {
    int i = blockIdx.x * blockDim.x + threadIdx.x;
    if (i < E) { atomicAdd(&g_co[src[i]], 1); atomicAdd(&g_ci[dst[i]], 1); }
}
__global__ void norm_kernel(int n) {
    int i = blockIdx.x * blockDim.x + threadIdx.x;
    if (i < n) {
        g_ns[i] = rsqrtf(fmaxf((float)g_co[i], 1.f));
        g_nd[i] = rsqrtf(fmaxf((float)g_ci[i], 1.f));
    }
}
__global__ void scan1_kernel(int n) {
    __shared__ int s[SCAN_BS];
    int t = threadIdx.x, i = blockIdx.x * SCAN_BS + t;
    int v = (i < n) ? g_ci[i] : 0;
    s[t] = v; __syncthreads();
#pragma unroll
    for (int off = 1; off < SCAN_BS; off <<= 1) {
        int x = (t >= off) ? s[t - off] : 0; __syncthreads();
        s[t] += x; __syncthreads();
    }
    if (i < n) g_rowptr[i] = s[t] - v;
    if (t == SCAN_BS - 1) g_bsum[blockIdx.x] = s[t];
}
__global__ void scan2_kernel(int nb) {
    __shared__ int s[512];
    int t = threadIdx.x;
    int v = (t < nb) ? g_bsum[t] : 0;
    s[t] = v; __syncthreads();
#pragma unroll
    for (int off = 1; off < 512; off <<= 1) {
        int x = (t >= off) ? s[t - off] : 0; __syncthreads();
        s[t] += x; __syncthreads();
    }
    if (t < nb) g_bsum[t] = s[t] - v;
}
__global__ void scan3_kernel(int n, int E) {
    int i = blockIdx.x * blockDim.x + threadIdx.x;
    if (i < n) {
        int r = g_rowptr[i] + g_bsum[i >> 8];
        g_rowptr[i] = r; g_cursor[i] = r;
    }
    if (i == 0) g_rowptr[n] = E;
}
__global__ void fill_kernel(const int* __restrict__ src,
                            const int* __restrict__ dst, int E) {
    int e = blockIdx.x * blockDim.x + threadIdx.x;
    if (e < E) {
        int pos = atomicAdd(&g_cursor[dst[e]], 1);
        g_esrc[pos] = src[e];
    }
}

// ---------------- Weight prep: transpose to [n][k], fp16 ----------------
__global__ void prep_w_kernel(const float* __restrict__ W1,
                              const float* __restrict__ W2) {
    int i = blockIdx.x * blockDim.x + threadIdx.x;
    if (i < FD * FD) {
        int k = i >> 7, n = i & 127;
        g_w1h[n * FD + k] = __float2half(W1[i]);
        g_w2h[n * FD + k] = __float2half(W2[i]);
    }
}

// ---------------- fp16 mma.sync GEMM: g_hh = A16 @ W16 (fp32 acc) ------------
// Layer 1: A = fp16(features * ns) computed on the fly.
// Layer 2: A = g_aggh (already fp16, already *ns) — straight copy.
#define ASTRIDE 136
#define TILE_B (128 * ASTRIDE * 2)   // 34816 bytes
#define OFF_A 0
#define OFF_B TILE_B
#define GEMM_SMEM (2 * TILE_B)       // 69632 bytes

__global__ __launch_bounds__(256) void gemm_mma_kernel(
    const float* __restrict__ Aext, int layer, int M) {
    extern __shared__ char sm[];
    const uint32_t sb = smem_u32(sm);
    const int tid = threadIdx.x;
    const int lane = tid & 31;
    const int wid = tid >> 5;
    const int row0 = blockIdx.x * 128;

    // ---- Fill A tile: thread handles row tid/2, 64-col half ----
    {
        int r = tid >> 1;
        int cs = (tid & 1) * 64;
        int grow = row0 + r;
        uint32_t base = (uint32_t)(r * ASTRIDE + cs) * 2;
        if (layer == 1) {
            if (grow < M) {
                float nm = g_ns[grow];
                const float4* ap = reinterpret_cast<const float4*>(Aext + (size_t)grow * FD + cs);
#pragma unroll
                for (int j = 0; j < 16; j++) {
                    float4 v = __ldg(&ap[j]);
                    __half2 p0 = __floats2half2_rn(v.x * nm, v.y * nm);
                    __half2 p1 = __floats2half2_rn(v.z * nm, v.w * nm);
                    uint32_t o = base + j * 8;
                    *reinterpret_cast<uint32_t*>(sm + OFF_A + o)     = *reinterpret_cast<uint32_t*>(&p0);
                    *reinterpret_cast<uint32_t*>(sm + OFF_A + o + 4) = *reinterpret_cast<uint32_t*>(&p1);
                }
            } else {
#pragma unroll
                for (int j = 0; j < 16; j++) {
                    uint32_t o = base + j * 8;
                    *reinterpret_cast<uint32_t*>(sm + OFF_A + o)     = 0u;
                    *reinterpret_cast<uint32_t*>(sm + OFF_A + o + 4) = 0u;
                }
            }
        } else {
            if (grow < M) {
                const uint4* ap = reinterpret_cast<const uint4*>(g_aggh + (size_t)grow * FD + cs);
#pragma unroll
                for (int j = 0; j < 8; j++)
                    *reinterpret_cast<uint4*>(sm + OFF_A + base + j * 16) = __ldg(&ap[j]);
            } else {
#pragma unroll
                for (int j = 0; j < 8; j++)
                    *reinterpret_cast<uint4*>(sm + OFF_A + base + j * 16) =
                        make_uint4(0u, 0u, 0u, 0u);
            }
        }
    }
    // ---- Fill B tile from pre-transposed fp16 weights [n][k] ----
    {
        const __half* wh = (layer == 1) ? g_w1h : g_w2h;
        int n = tid >> 1;
        int cs = (tid & 1) * 64;
        uint32_t base = (uint32_t)(n * ASTRIDE + cs) * 2;
        const uint4* ph = reinterpret_cast<const uint4*>(wh + (size_t)n * FD + cs);
#pragma unroll
        for (int j = 0; j < 8; j++)
            *reinterpret_cast<uint4*>(sm + OFF_B + base + j * 16) = __ldg(&ph[j]);
    }
    __syncthreads();

    // ---- Mainloop: warp tile 64x32, 8 warps (2x4) ----
    const int m0 = (wid >> 2) * 64;
    const int n0 = (wid & 3) * 32;

    float acc[4][4][4];
#pragma unroll
    for (int mi = 0; mi < 4; mi++)
#pragma unroll
        for (int ni = 0; ni < 4; ni++)
#pragma unroll
            for (int q = 0; q < 4; q++) acc[mi][ni][q] = 0.f;

    const uint32_t aOff = (uint32_t)((m0 + (lane & 15)) * ASTRIDE + ((lane >> 4) << 3)) * 2;
    const uint32_t bOff = (uint32_t)((n0 + (lane & 7)) * ASTRIDE + (((lane >> 3) & 1) << 3)) * 2;
    const uint32_t aBase = sb + OFF_A + aOff;
    const uint32_t bBase = sb + OFF_B + bOff;

#pragma unroll
    for (int ks = 0; ks < 8; ks++) {
        const uint32_t ka = ks * 32;
        uint32_t a[4][4], b[4][2];
#pragma unroll
        for (int mi = 0; mi < 4; mi++)
            LDSM4(a[mi][0], a[mi][1], a[mi][2], a[mi][3], aBase + mi * (16 * ASTRIDE * 2) + ka);
#pragma unroll
        for (int ni = 0; ni < 4; ni++)
            LDSM2(b[ni][0], b[ni][1], bBase + ni * (8 * ASTRIDE * 2) + ka);
#pragma unroll
        for (int mi = 0; mi < 4; mi++)
#pragma unroll
            for (int ni = 0; ni < 4; ni++)
                mma16816(acc[mi][ni], a[mi], b[ni]);
    }

    // ---- Epilogue: fragment -> g_hh (fp16) ----
    const int rb = m0 + (lane >> 2);
    const int cb = n0 + (lane & 3) * 2;
#pragma unroll
    for (int mi = 0; mi < 4; mi++) {
        int r0g = row0 + rb + mi * 16;
#pragma unroll
        for (int ni = 0; ni < 4; ni++) {
            int col = cb + ni * 8;
            if (r0g < M)
                *reinterpret_cast<__half2*>(g_hh + (size_t)r0g * FD + col) =
                    __floats2half2_rn(acc[mi][ni][0], acc[mi][ni][1]);
            if (r0g + 8 < M)
                *reinterpret_cast<__half2*>(g_hh + (size_t)(r0g + 8) * FD + col) =
                    __floats2half2_rn(acc[mi][ni][2], acc[mi][ni][3]);
        }
    }
}

// ---------------- CSR aggregate (fp16 messages) + fused epilogue -------------
// Layer 1 (out==nullptr): g_aggh = fp16(relu(acc*nd + b) * ns)   [ns folded in]
// Layer 2: out = acc*nd + b  (fp32)
__global__ __launch_bounds__(256) void agg_kernel(
    const float* __restrict__ bvec, float* __restrict__ out, int M) {
    const int warp = (blockIdx.x * blockDim.x + threadIdx.x) >> 5;
    const int lane = threadIdx.x & 31;
    if (warp >= M) return;

    const int beg = __ldg(&g_rowptr[warp]);
    const int end = __ldg(&g_rowptr[warp + 1]);

    float4 acc = make_float4(0.f, 0.f, 0.f, 0.f);
    int j = beg;
    for (; j + 3 < end; j += 4) {
        int s0 = __ldg(&g_esrc[j]);
        int s1 = __ldg(&g_esrc[j + 1]);
        int s2 = __ldg(&g_esrc[j + 2]);
        int s3 = __ldg(&g_esrc[j + 3]);
        uint2 u0 = __ldg(reinterpret_cast<const uint2*>(g_hh + (size_t)s0 * FD) + lane);
        uint2 u1 = __ldg(reinterpret_cast<const uint2*>(g_hh + (size_t)s1 * FD) + lane);
        uint2 u2 = __ldg(reinterpret_cast<const uint2*>(g_hh + (size_t)s2 * FD) + lane);
        uint2 u3 = __ldg(reinterpret_cast<const uint2*>(g_hh + (size_t)s3 * FD) + lane);
#pragma unroll
        for (int q = 0; q < 4; q++) {
            uint2 u = (q == 0) ? u0 : (q == 1) ? u1 : (q == 2) ? u2 : u3;
            float2 fa = __half22float2(*reinterpret_cast<__half2*>(&u.x));
            float2 fb = __half22float2(*reinterpret_cast<__half2*>(&u.y));
            acc.x += fa.x; acc.y += fa.y; acc.z += fb.x; acc.w += fb.y;
        }
    }
    for (; j < end; j++) {
        int s0 = __ldg(&g_esrc[j]);
        uint2 u = __ldg(reinterpret_cast<const uint2*>(g_hh + (size_t)s0 * FD) + lane);
        float2 fa = __half22float2(*reinterpret_cast<__half2*>(&u.x));
        float2 fb = __half22float2(*reinterpret_cast<__half2*>(&u.y));
        acc.x += fa.x; acc.y += fa.y; acc.z += fb.x; acc.w += fb.y;
    }

    const float nd = g_nd[warp];
    const float4 bb = __ldg(reinterpret_cast<const float4*>(bvec) + lane);
    acc.x = acc.x * nd + bb.x; acc.y = acc.y * nd + bb.y;
    acc.z = acc.z * nd + bb.z; acc.w = acc.w * nd + bb.w;

    if (out) {
        reinterpret_cast<float4*>(out + (size_t)warp * FD)[lane] = acc;
    } else {
        const float ns = g_ns[warp];
        acc.x = fmaxf(acc.x, 0.f) * ns; acc.y = fmaxf(acc.y, 0.f) * ns;
        acc.z = fmaxf(acc.z, 0.f) * ns; acc.w = fmaxf(acc.w, 0.f) * ns;
        __half2 p0 = __floats2half2_rn(acc.x, acc.y);
        __half2 p1 = __floats2half2_rn(acc.z, acc.w);
        uint2 u;
        u.x = *reinterpret_cast<uint32_t*>(&p0);
        u.y = *reinterpret_cast<uint32_t*>(&p1);
        reinterpret_cast<uint2*>(g_aggh + (size_t)warp * FD)[lane] = u;
    }
}

// ---------------- Launch ----------------
extern "C" void kernel_launch(void* const* d_in, const int* in_sizes, int n_in,
                              void* d_out, int out_size) {
    const float* features = (const float*)d_in[0];
    const int* src = (const int*)d_in[1];
    const int* dst = (const int*)d_in[2];
    const float* W1 = (const float*)d_in[3];
    const float* b1 = (const float*)d_in[4];
    const float* W2 = (const float*)d_in[5];
    const float* b2 = (const float*)d_in[6];
    float* out = (float*)d_out;

    const int M = in_sizes[0] / FD;   // 100000
    const int E = in_sizes[1];        // 1600000

    // One-time resource setup (host objects only; no device memory)
    static cudaStream_t s2 = nullptr;
    static cudaEvent_t evA = nullptr, evB = nullptr;
    if (!s2) {
        cudaStreamCreateWithFlags(&s2, cudaStreamNonBlocking);
        cudaEventCreateWithFlags(&evA, cudaEventDisableTiming);
        cudaEventCreateWithFlags(&evB, cudaEventDisableTiming);
        cudaFuncSetAttribute(gemm_mma_kernel,
                             cudaFuncAttributeMaxDynamicSharedMemorySize, GEMM_SMEM);
    }

    const int T = 256;
    const int mb = (M + T - 1) / T;
    const int eb = (E + T - 1) / T;

    // Legacy stream: degrees (needed by both branches)
    zero_cnt_kernel<<<mb, T>>>(M);
    degree_kernel<<<eb, T>>>(src, dst, E);
    cudaEventRecord(evA, (cudaStream_t)0);

    // Fork: CSR build on s2, concurrent with norm+prep+gemm1
    cudaStreamWaitEvent(s2, evA, 0);
    scan1_kernel<<<NB1, SCAN_BS, 0, s2>>>(M);
    scan2_kernel<<<1, 512, 0, s2>>>(NB1);
    scan3_kernel<<<mb, T, 0, s2>>>(M, E);
    fill_kernel<<<eb, T, 0, s2>>>(src, dst, E);
    cudaEventRecord(evB, s2);

    // Legacy stream: norms, weight prep, layer-1 GEMM
    norm_kernel<<<mb, T>>>(M);
    prep_w_kernel<<<(FD * FD + T - 1) / T, T>>>(W1, W2);

    const int gemm_blocks = (M + 127) / 128;        // 782
    const int agg_blocks = (M * 32 + T - 1) / T;    // one warp per node

    gemm_mma_kernel<<<gemm_blocks, 256, GEMM_SMEM>>>(features, 1, M);

    // Join: agg1 needs the CSR
    cudaStreamWaitEvent((cudaStream_t)0, evB, 0);
    agg_kernel<<<agg_blocks, T>>>(b1, nullptr, M);

    // Layer 2
    gemm_mma_kernel<<<gemm_blocks, 256, GEMM_SMEM>>>(nullptr, 2, M);
    agg_kernel<<<agg_blocks, T>>>(b2, out, M);
}